// round 15
// baseline (speedup 1.0000x reference)
#include <cuda_runtime.h>
#include <cuda_bf16.h>
#include <cstdint>

#define NB 32
#define NC 64
#define NS 128
#define NZ 64
#define ND 256
#define VO 5000
#define VOP 5120

typedef __nv_bfloat16 bf16;

// ---- pair-kernel smem byte offsets (103,712 B -> 2 CTAs/SM) ----
#define OB_AM    0
#define OB_BM    67584
#define OB_BETA  0
#define OB_ALPT  18432
#define OB_BG2T  35840
#define OB_ST7   72704
#define OB_E     72704
#define OB_CID   101376
#define OB_HW    101632
#define OB_RED   103680
#define SMEM_PAIR 103712

// pitches (bf16 elements)
#define P_AM   264
#define P_BM   264
#define P_E    72
#define P_BETA 72
#define P_BG2T 72
#define P_ALPT 136
#define P_ST7  24

// tables kernel smem (floats)
#define TA_PITCH 260
#define TW_PITCH 264
#define T_WST_OFF (64*TA_PITCH)
#define T_SMEM_FL (64*TA_PITCH + 16*TW_PITCH)

// ---------------- device scratch ----------------
__device__ bf16  g_am  [NB*NS*ND];     // relu(a@FW+Fb) [b][s][k]
__device__ bf16  g_aG1h[NB*NS*ND];     // bf16(a@GW1+Gb) [b][s][g]
__device__ bf16  g_aG2C[NB*8*ND*16];   // (a@GW2)^T chunk-major [b][sc][g][16]
__device__ bf16  g_bm  [VOP*ND];
__device__ bf16  g_bg1h[VOP*ND];       // bf16(EmbB@GW1+Gb)
__device__ bf16  g_bg2 [VOP*ND];

// ---------------- helpers ----------------
__device__ __forceinline__ uint32_t f2t(float f){
    uint32_t u; asm("cvt.rna.tf32.f32 %0, %1;" : "=r"(u) : "f"(f)); return u;
}
__device__ __forceinline__ float rtf(float f){ return __uint_as_float(f2t(f)); }
__device__ __forceinline__ uint32_t ldu(const float* p){ return __float_as_uint(*p); }
__device__ __forceinline__ uint32_t ldb(const bf16* p){
    return *reinterpret_cast<const uint32_t*>(p);
}
__device__ __forceinline__ uint32_t pkf(float a, float b){
    __nv_bfloat162 t = __floats2bfloat162_rn(a, b);
    return *reinterpret_cast<uint32_t*>(&t);
}
__device__ __forceinline__ uint32_t pkh(bf16 a, bf16 b){
    __nv_bfloat162 t = __halves2bfloat162(a, b);
    return *reinterpret_cast<uint32_t*>(&t);
}
__device__ __forceinline__ float2 upk(uint32_t u){
    __nv_bfloat162 t = *reinterpret_cast<__nv_bfloat162*>(&u);
    return __bfloat1622float2(t);
}
__device__ __forceinline__ float b2f(bf16 v){ return __bfloat162float(v); }
__device__ __forceinline__ uint32_t smaddr(const void* p){
    return (uint32_t)__cvta_generic_to_shared(p);
}
__device__ __forceinline__ void ldsm4(uint32_t& r0,uint32_t& r1,uint32_t& r2,uint32_t& r3,
                                      uint32_t a){
    asm volatile("ldmatrix.sync.aligned.m8n8.x4.shared.b16 {%0,%1,%2,%3}, [%4];"
        : "=r"(r0),"=r"(r1),"=r"(r2),"=r"(r3) : "r"(a));
}

// tf32 m16n8k8
__device__ __forceinline__ void mma8(float* d,
    uint32_t a0,uint32_t a1,uint32_t a2,uint32_t a3, uint32_t b0,uint32_t b1){
    asm volatile("mma.sync.aligned.m16n8k8.row.col.f32.tf32.tf32.f32 "
        "{%0,%1,%2,%3}, {%4,%5,%6,%7}, {%8,%9}, {%0,%1,%2,%3};\n"
        : "+f"(d[0]),"+f"(d[1]),"+f"(d[2]),"+f"(d[3])
        : "r"(a0),"r"(a1),"r"(a2),"r"(a3),"r"(b0),"r"(b1));
}
// bf16 m16n8k16
__device__ __forceinline__ void mmab(float* d,
    uint32_t a0,uint32_t a1,uint32_t a2,uint32_t a3, uint32_t b0,uint32_t b1){
    asm volatile("mma.sync.aligned.m16n8k16.row.col.f32.bf16.bf16.f32 "
        "{%0,%1,%2,%3}, {%4,%5,%6,%7}, {%8,%9}, {%0,%1,%2,%3};\n"
        : "+f"(d[0]),"+f"(d[1]),"+f"(d[2]),"+f"(d[3])
        : "r"(a0),"r"(a1),"r"(a2),"r"(a3),"r"(b0),"r"(b1));
}

__device__ __forceinline__ uint32_t a_lds_addr(const bf16* buf, int row0, int kbase,
                                               int pitch, int lane){
    int row  = row0 + (lane & 15);
    int half = lane >> 4;
    return smaddr(buf + row*pitch + kbase + half*8);
}
__device__ __forceinline__ uint32_t b_lds_addr(const bf16* buf, int n0, int kbase,
                                               int pitch, int lane){
    int nrow = n0 + (lane & 7) + ((lane >> 4) << 3);
    int half = (lane >> 3) & 1;
    return smaddr(buf + nrow*pitch + kbase + half*8);
}

// =========================================================================
// Tables kernel (tf32 mma). grid=(12, 144), 256 thr.
// m: 0 F+relu -> g_am/g_bm (bf16); 1 GW1+Gb -> g_aG1h/g_bg1h (bf16, exact->round);
//    2 GW2 -> a-side g_aG2C (transposed chunk-major) / b-side g_bg2
// =========================================================================
__global__ void __launch_bounds__(256) tables_kernel(
    const int*   __restrict__ inptensor,
    const float* __restrict__ EmbA,
    const float* __restrict__ EmbB,
    const float* __restrict__ FW,
    const float* __restrict__ Fb,
    const float* __restrict__ GW,
    const float* __restrict__ Gb)
{
    extern __shared__ float sm[];
    float* a_tile = sm;
    float* wst    = sm + T_WST_OFF;

    const int y     = blockIdx.y;
    const int chunk = blockIdx.x;
    const int m     = chunk >> 2;
    const int gbase = (chunk & 3) * 64;
    const int tid   = threadIdx.x;
    const bool aside = (y < 2*NB);
    const int w    = tid >> 5;
    const int lane = tid & 31;
    const int r    = lane >> 2;
    const int c    = lane & 3;
    const int wm   = w >> 1;
    const int wn   = w & 1;

    if (aside) {
        const int b = y >> 1, sh = (y & 1) * 64;
        for (int s = 0; s < 64; s++) {
            int idx = __ldg(&inptensor[b*NS + sh + s]);
            a_tile[s*TA_PITCH + tid] = rtf(__ldg(&EmbA[(size_t)idx*ND + tid]));
        }
    } else {
        const int rt = y - 2*NB;
        for (int s = 0; s < 64; s++) {
            int row = rt*64 + s;
            int rr = (row < VO) ? row : 0;
            a_tile[s*TA_PITCH + tid] = rtf(__ldg(&EmbB[(size_t)rr*ND + tid]));
        }
    }
    __syncthreads();

    const float* Wsrc = (m == 0) ? FW : GW;
    const int wrow_off = (m == 2) ? 256 : 0;

    float acc[4][4];
    #pragma unroll
    for (int f = 0; f < 4; f++)
        #pragma unroll
        for (int e = 0; e < 4; e++) acc[f][e] = 0.f;

    for (int t = 0; t < 16; t++) {
        int k0 = t*16;
        #pragma unroll
        for (int q = 0; q < 4; q++) {
            int idx2 = tid + 256*q;
            int kk = idx2 >> 6, gg = idx2 & 63;
            wst[kk*TW_PITCH + gg] =
                rtf(__ldg(&Wsrc[(size_t)(k0 + kk + wrow_off)*256 + gbase + gg]));
        }
        __syncthreads();
        #pragma unroll
        for (int kh = 0; kh < 2; kh++) {
            const float* ap = a_tile + (wm*16 + r)*TA_PITCH + k0 + kh*8 + c;
            uint32_t a0 = ldu(ap), a1 = ldu(ap + 8*TA_PITCH);
            uint32_t a2 = ldu(ap + 4), a3 = ldu(ap + 8*TA_PITCH + 4);
            #pragma unroll
            for (int f = 0; f < 4; f++) {
                const float* bp = wst + (kh*8 + c)*TW_PITCH + wn*32 + f*8 + r;
                mma8(acc[f], a0,a1,a2,a3, ldu(bp), ldu(bp + 4*TW_PITCH));
            }
        }
        __syncthreads();
    }

    const int b_ = y >> 1, sh = (y & 1) * 64;
    const int rt = y - 2*NB;
    const int lr0 = wm*16 + r;

    if (m == 2 && aside) {
        bf16* tbuf = (bf16*)a_tile;     // [64 g][66 s]
        #pragma unroll
        for (int f = 0; f < 4; f++) {
            int lc = wn*32 + f*8 + c*2;
            tbuf[lc*66 + lr0]       = __float2bfloat16_rn(acc[f][0]);
            tbuf[(lc+1)*66 + lr0]   = __float2bfloat16_rn(acc[f][1]);
            tbuf[lc*66 + lr0+8]     = __float2bfloat16_rn(acc[f][2]);
            tbuf[(lc+1)*66 + lr0+8] = __float2bfloat16_rn(acc[f][3]);
        }
        __syncthreads();
        int gl = tid >> 2;
        int sc4 = tid & 3;
        int scG = (sh >> 4) + sc4;
        const uint32_t* src = (const uint32_t*)(tbuf + gl*66 + sc4*16);
        uint32_t v0=src[0],v1=src[1],v2=src[2],v3=src[3];
        uint32_t v4=src[4],v5=src[5],v6=src[6],v7=src[7];
        uint4* dst = (uint4*)(g_aG2C + (((size_t)b_*8 + scG)*ND + gbase + gl)*16);
        dst[0] = make_uint4(v0,v1,v2,v3);
        dst[1] = make_uint4(v4,v5,v6,v7);
        return;
    }

    #pragma unroll
    for (int f = 0; f < 4; f++) {
        int col = gbase + wn*32 + f*8 + c*2;
        float b0 = (m == 0) ? __ldg(&Fb[col])   : (m == 1 ? __ldg(&Gb[col])   : 0.f);
        float b1 = (m == 0) ? __ldg(&Fb[col+1]) : (m == 1 ? __ldg(&Gb[col+1]) : 0.f);
        float v00 = acc[f][0] + b0, v01 = acc[f][1] + b1;
        float v10 = acc[f][2] + b0, v11 = acc[f][3] + b1;
        if (m == 0) {
            v00 = fmaxf(v00, 0.f); v01 = fmaxf(v01, 0.f);
            v10 = fmaxf(v10, 0.f); v11 = fmaxf(v11, 0.f);
        }
        int row0 = aside ? (sh + lr0) : (rt*64 + lr0);
        int row1 = row0 + 8;
        bf16* outp;
        if (m == 0)      outp = aside ? (g_am   + (size_t)b_*NS*ND) : g_bm;
        else if (m == 1) outp = aside ? (g_aG1h + (size_t)b_*NS*ND) : g_bg1h;
        else             outp = g_bg2;   // m==2 b-side
        *(uint32_t*)(outp + (size_t)row0*ND + col) = pkf(v00, v01);
        *(uint32_t*)(outp + (size_t)row1*ND + col) = pkf(v10, v11);
    }
}

// =========================================================================
// Pair kernel: one CTA per (b,c). 256 threads / 8 warps, 2 CTAs per SM.
// =========================================================================
__global__ void __launch_bounds__(256, 2) pair_kernel(
    const int*   __restrict__ cand,
    const float* __restrict__ HW,
    const float* __restrict__ Hb,
    float*       __restrict__ out)
{
    extern __shared__ char smc[];
    bf16*  s_am   = (bf16*) (smc + OB_AM);
    bf16*  s_bm   = (bf16*) (smc + OB_BM);
    bf16*  s_e    = (bf16*) (smc + OB_E);
    bf16*  s_beta = (bf16*) (smc + OB_BETA);
    bf16*  s_alpt = (bf16*) (smc + OB_ALPT);
    bf16*  s_bg2t = (bf16*) (smc + OB_BG2T);
    bf16*  s_st7  = (bf16*) (smc + OB_ST7);
    int*   s_cid  = (int*)  (smc + OB_CID);
    float* sHW    = (float*)(smc + OB_HW);
    float* sRed   = (float*)(smc + OB_RED);

    const int tid  = threadIdx.x;
    const int p    = blockIdx.x;
    const int b    = p >> 6;
    const int w    = tid >> 5;
    const int lane = tid & 31;
    const int r    = lane >> 2;
    const int c    = lane & 3;

    sHW[tid] = __ldg(&HW[tid]);
    sHW[tid + 256] = __ldg(&HW[tid + 256]);
    if (tid < 64) s_cid[tid] = __ldg(&cand[p*NZ + tid]);

    // ---- P1: stage full a_m + gather b_m ----
    {
        const uint4* src = (const uint4*)(g_am + (size_t)b*NS*ND);
        #pragma unroll
        for (int t = 0; t < 16; t++) {
            int idx = tid + 256*t;
            int row = idx >> 5, c8 = (idx & 31) * 8;
            *(uint4*)(s_am + row*P_AM + c8) = __ldg(&src[idx]);
        }
        #pragma unroll
        for (int t = 0; t < 8; t++) {
            int idx = tid + 256*t;
            int z = idx >> 5, c8 = (idx & 31) * 8;
            int id = __ldg(&cand[p*NZ + z]);
            *(uint4*)(s_bm + z*P_BM + c8) = __ldg((const uint4*)(g_bm + (size_t)id*ND + c8));
        }
    }
    __syncthreads();

    // ---- P3: e = a_m @ b_m^T, sync-free ----
    float eacc[2][4][4];
    {
        const int wm = w >> 1;
        const int wn = w & 1;
        #pragma unroll
        for (int mi=0;mi<2;mi++)
            #pragma unroll
            for (int f=0;f<4;f++)
                #pragma unroll
                for (int e=0;e<4;e++) eacc[mi][f][e]=0.f;

        #pragma unroll 4
        for (int ks = 0; ks < 16; ks++) {
            uint32_t af[2][4];
            #pragma unroll
            for (int mi = 0; mi < 2; mi++)
                ldsm4(af[mi][0],af[mi][1],af[mi][2],af[mi][3],
                      a_lds_addr(s_am, wm*32 + mi*16, ks*16, P_AM, lane));
            uint32_t bfr[4][2];
            #pragma unroll
            for (int fp = 0; fp < 2; fp++)
                ldsm4(bfr[2*fp][0],bfr[2*fp][1],bfr[2*fp+1][0],bfr[2*fp+1][1],
                      b_lds_addr(s_bm, wn*32 + fp*16, ks*16, P_BM, lane));
            #pragma unroll
            for (int mi = 0; mi < 2; mi++)
                #pragma unroll
                for (int f = 0; f < 4; f++)
                    mmab(eacc[mi][f], af[mi][0],af[mi][1],af[mi][2],af[mi][3],
                         bfr[f][0], bfr[f][1]);
        }
    }
    __syncthreads();

    {
        const int wm = w >> 1;
        const int wn = w & 1;
        #pragma unroll
        for (int mi=0;mi<2;mi++)
            #pragma unroll
            for (int f=0;f<4;f++){
                int row0 = wm*32 + mi*16 + r;
                int col0 = wn*32 + f*8 + 2*c;
                *(uint32_t*)(s_e + row0*P_E + col0)     = pkf(eacc[mi][f][0], eacc[mi][f][1]);
                *(uint32_t*)(s_e + (row0+8)*P_E + col0) = pkf(eacc[mi][f][2], eacc[mi][f][3]);
            }
    }
    __syncthreads();

    // ---- P4a: beta = softmax over z (rows) ----
    {
        #pragma unroll
        for (int rr = 0; rr < 16; rr++) {
            int s = w*16 + rr;
            float v0 = b2f(s_e[s*P_E + lane]);
            float v1 = b2f(s_e[s*P_E + lane + 32]);
            float mx = fmaxf(v0, v1);
            #pragma unroll
            for (int off = 16; off >= 1; off >>= 1)
                mx = fmaxf(mx, __shfl_xor_sync(0xffffffffu, mx, off));
            float e0 = __expf(v0 - mx), e1 = __expf(v1 - mx);
            float ss = e0 + e1;
            #pragma unroll
            for (int off = 16; off >= 1; off >>= 1)
                ss += __shfl_xor_sync(0xffffffffu, ss, off);
            float inv = 1.f / ss;
            s_beta[s*P_BETA + lane]      = __float2bfloat16_rn(e0 * inv);
            s_beta[s*P_BETA + lane + 32] = __float2bfloat16_rn(e1 * inv);
        }
    }

    // ---- P4b: alpha = softmax over s (cols) -> s_alpt transposed ----
    {
        const int z = tid >> 2, q = tid & 3;
        float ev[32];
        float mx = -1e30f;
        #pragma unroll
        for (int i = 0; i < 32; i++) {
            ev[i] = b2f(s_e[(q*32 + i)*P_E + z]);
            mx = fmaxf(mx, ev[i]);
        }
        mx = fmaxf(mx, __shfl_xor_sync(0xffffffffu, mx, 1));
        mx = fmaxf(mx, __shfl_xor_sync(0xffffffffu, mx, 2));
        float ss = 0.f;
        #pragma unroll
        for (int i = 0; i < 32; i++) { ev[i] = __expf(ev[i] - mx); ss += ev[i]; }
        ss += __shfl_xor_sync(0xffffffffu, ss, 1);
        ss += __shfl_xor_sync(0xffffffffu, ss, 2);
        float inv = 1.f / ss;
        #pragma unroll
        for (int i = 0; i < 16; i++) {
            *(uint32_t*)(s_alpt + z*P_ALPT + q*32 + 2*i) =
                pkf(ev[2*i]*inv, ev[2*i+1]*inv);
        }
    }
    __syncthreads();

    // ---- gather bbG2^T + stage st7 chunk 0 ----
    {
        const int g = tid;
        #pragma unroll
        for (int t = 0; t < 32; t++) {
            int z0 = 2*t;
            int id0 = s_cid[z0], id1 = s_cid[z0+1];
            bf16 v0 = __ldg(g_bg2 + (size_t)id0*ND + g);
            bf16 v1 = __ldg(g_bg2 + (size_t)id1*ND + g);
            *(uint32_t*)(s_bg2t + g*P_BG2T + z0) = pkh(v0, v1);
        }
        const uint4* src = (const uint4*)(g_aG2C + (((size_t)b*8 + 0)*ND + g)*16);
        uint4 v0 = __ldg(src), v1 = __ldg(src+1);
        *(uint4*)(s_st7 + g*P_ST7)     = v0;
        *(uint4*)(s_st7 + g*P_ST7 + 8) = v1;
    }
    __syncthreads();

    float y_local = 0.f;

    // ---- P6: y1 += sum relu(aG1 + beta @ bbG2) * HW1 ----
    {
        const int wm = w >> 1;
        const int wn = w & 1;
        const bf16* aG1p = g_aG1h + (size_t)b*NS*ND;
        #pragma unroll
        for (int pass = 0; pass < 2; pass++){
            int nb = wn*128 + pass*64;
            float acc[2][8][4];
            #pragma unroll
            for (int mi=0;mi<2;mi++)
                #pragma unroll
                for (int f=0;f<8;f++)
                    #pragma unroll
                    for (int e=0;e<4;e++) acc[mi][f][e]=0.f;
            #pragma unroll
            for (int kz = 0; kz < 4; kz++) {
                uint32_t af[2][4];
                #pragma unroll
                for (int mi = 0; mi < 2; mi++)
                    ldsm4(af[mi][0],af[mi][1],af[mi][2],af[mi][3],
                          a_lds_addr(s_beta, wm*32 + mi*16, kz*16, P_BETA, lane));
                uint32_t bfr[8][2];
                #pragma unroll
                for (int fp = 0; fp < 4; fp++)
                    ldsm4(bfr[2*fp][0],bfr[2*fp][1],bfr[2*fp+1][0],bfr[2*fp+1][1],
                          b_lds_addr(s_bg2t, nb + fp*16, kz*16, P_BG2T, lane));
                #pragma unroll
                for (int mi = 0; mi < 2; mi++)
                    #pragma unroll
                    for (int f = 0; f < 8; f++)
                        mmab(acc[mi][f], af[mi][0],af[mi][1],af[mi][2],af[mi][3],
                             bfr[f][0], bfr[f][1]);
            }
            #pragma unroll
            for (int mi=0;mi<2;mi++)
                #pragma unroll
                for (int f=0;f<8;f++){
                    int row0 = wm*32 + mi*16 + r;
                    int col0 = nb + f*8 + 2*c;
                    float2 g0 = upk(ldb(aG1p + (size_t)row0*ND + col0));
                    float2 g1 = upk(ldb(aG1p + (size_t)(row0+8)*ND + col0));
                    float h0 = sHW[col0], h1 = sHW[col0+1];
                    y_local += fmaxf(acc[mi][f][0] + g0.x, 0.f)*h0
                             + fmaxf(acc[mi][f][1] + g0.y, 0.f)*h1
                             + fmaxf(acc[mi][f][2] + g1.x, 0.f)*h0
                             + fmaxf(acc[mi][f][3] + g1.y, 0.f)*h1;
                }
        }
    }

    // ---- P7: y2 += sum relu(bG1 + alpha^T @ aG2) * HW2, chunked K over s ----
    {
        const int wm = w >> 2;
        const int wn = w & 3;
        float acc[2][8][4];
        #pragma unroll
        for (int mi=0;mi<2;mi++)
            #pragma unroll
            for (int f=0;f<8;f++){
                int row0 = wm*32 + mi*16 + r;
                int col0 = wn*64 + f*8 + 2*c;
                int id0 = s_cid[row0], id1 = s_cid[row0+8];
                float2 u0 = upk(ldb(g_bg1h + (size_t)id0*ND + col0));
                float2 u1 = upk(ldb(g_bg1h + (size_t)id1*ND + col0));
                acc[mi][f][0]=u0.x; acc[mi][f][1]=u0.y;
                acc[mi][f][2]=u1.x; acc[mi][f][3]=u1.y;
            }
        const int g = tid;
        for (int t = 0; t < 8; t++) {
            if (t < 7) {
                const uint4* src = (const uint4*)(g_aG2C + (((size_t)b*8 + t+1)*ND + g)*16);
                uint4 v0 = __ldg(src), v1 = __ldg(src+1);
                bf16* dst = s_st7 + ((t+1)&1)*ND*P_ST7 + g*P_ST7;
                *(uint4*)(dst)     = v0;
                *(uint4*)(dst + 8) = v1;
            }
            const bf16* cb = s_st7 + (t&1)*ND*P_ST7;
            uint32_t af[2][4];
            #pragma unroll
            for (int mi = 0; mi < 2; mi++)
                ldsm4(af[mi][0],af[mi][1],af[mi][2],af[mi][3],
                      a_lds_addr(s_alpt, wm*32 + mi*16, t*16, P_ALPT, lane));
            uint32_t bfr[8][2];
            #pragma unroll
            for (int fp = 0; fp < 4; fp++)
                ldsm4(bfr[2*fp][0],bfr[2*fp][1],bfr[2*fp+1][0],bfr[2*fp+1][1],
                      b_lds_addr(cb, wn*64 + fp*16, 0, P_ST7, lane));
            #pragma unroll
            for (int mi = 0; mi < 2; mi++)
                #pragma unroll
                for (int f = 0; f < 8; f++)
                    mmab(acc[mi][f], af[mi][0],af[mi][1],af[mi][2],af[mi][3],
                         bfr[f][0], bfr[f][1]);
            __syncthreads();
        }
        #pragma unroll
        for (int mi=0;mi<2;mi++)
            #pragma unroll
            for (int f=0;f<8;f++){
                int col0 = wn*64 + f*8 + 2*c;
                float h0 = sHW[256+col0], h1 = sHW[256+col0+1];
                y_local += fmaxf(acc[mi][f][0], 0.f)*h0
                         + fmaxf(acc[mi][f][1], 0.f)*h1
                         + fmaxf(acc[mi][f][2], 0.f)*h0
                         + fmaxf(acc[mi][f][3], 0.f)*h1;
            }
    }

    // ---- block reduce ----
    {
        #pragma unroll
        for (int off = 16; off >= 1; off >>= 1)
            y_local += __shfl_xor_sync(0xffffffffu, y_local, off);
        if (lane == 0) sRed[w] = y_local;
        __syncthreads();
        if (tid == 0) {
            float t = 0.f;
            #pragma unroll
            for (int ww = 0; ww < 8; ww++) t += sRed[ww];
            out[p] = t + __ldg(&Hb[0]);
        }
    }
}

// =========================================================================
extern "C" void kernel_launch(void* const* d_in, const int* in_sizes, int n_in,
                              void* d_out, int out_size)
{
    const int*   inptensor = (const int*)  d_in[0];
    const int*   cand      = (const int*)  d_in[1];
    const float* EmbA      = (const float*)d_in[4];
    const float* EmbB      = (const float*)d_in[5];
    const float* FW        = (const float*)d_in[6];
    const float* Fb        = (const float*)d_in[7];
    const float* GW        = (const float*)d_in[8];
    const float* Gb        = (const float*)d_in[9];
    const float* HW        = (const float*)d_in[10];
    const float* Hb        = (const float*)d_in[11];
    float*       out       = (float*)d_out;

    (void)in_sizes; (void)n_in; (void)out_size;

    const int smem1 = T_SMEM_FL * 4;
    cudaFuncSetAttribute(tables_kernel, cudaFuncAttributeMaxDynamicSharedMemorySize, smem1);
    cudaFuncSetAttribute(pair_kernel,   cudaFuncAttributeMaxDynamicSharedMemorySize, SMEM_PAIR);

    tables_kernel<<<dim3(12, 2*NB + VOP/64), 256, smem1>>>(
        inptensor, EmbA, EmbB, FW, Fb, GW, Gb);
    pair_kernel<<<NB*NC, 256, SMEM_PAIR>>>(cand, HW, Hb, out);
}